// round 9
// baseline (speedup 1.0000x reference)
#include <cuda_runtime.h>
#include <cuda_fp16.h>
#include <math.h>
#include <stdint.h>

// ---------------------------------------------------------------------------
// Problem constants
// ---------------------------------------------------------------------------
#define BATCH 32
#define CIN   256
#define COUT  256
#define HW_H  56
#define HW_W  56
#define HW    3136
#define KTAPS 9
#define M_TOT (BATCH * HW)               // 100352

#define M_TILE   128
#define THREADS  256                     // 8 warps: 255-reg budget
#define KC       64                      // ci per K chunk (4 k16 steps)
#define NCHUNKS  (KTAPS * (CIN / KC))    // 36
#define A_BYTES  (M_TILE * KC * 2)       // 16384
#define B_BYTES  (COUT * KC * 2)         // 32768
#define STAGE_BYTES (A_BYTES + B_BYTES)  // 49152
#define SMEM_DYN (3 * STAGE_BYTES)       // 147456

// ---------------------------------------------------------------------------
// Global scratch
// ---------------------------------------------------------------------------
__device__ __align__(16) __half g_a[(size_t)M_TOT * CIN];    // NHWC fp16
__device__ __align__(16) __half g_w[KTAPS * COUT * CIN];     // [tap][oc][ci]

// ---------------------------------------------------------------------------
// PTX helpers (compute_103-safe: sm_80-class features only)
// ---------------------------------------------------------------------------
__device__ __forceinline__ uint32_t smem_u32(const void* p) {
    uint32_t a;
    asm("{ .reg .u64 t; cvta.to.shared.u64 t, %1; cvt.u32.u64 %0, t; }"
        : "=r"(a) : "l"(p));
    return a;
}
#define CP_ASYNC16(dst, src, sz) \
    asm volatile("cp.async.ca.shared.global [%0], [%1], 16, %2;" \
        :: "r"(dst), "l"(src), "r"(sz) : "memory")
#define CP_COMMIT() asm volatile("cp.async.commit_group;" ::: "memory")
#define CP_WAIT1()  asm volatile("cp.async.wait_group 1;" ::: "memory")

#define LDSM_X4(r, addr) \
    asm volatile("ldmatrix.sync.aligned.m8n8.x4.shared.b16 {%0,%1,%2,%3}, [%4];" \
        : "=r"((r)[0]), "=r"((r)[1]), "=r"((r)[2]), "=r"((r)[3]) : "r"(addr))

#define MMA16816(d, a, b0v, b1v) \
    asm volatile("mma.sync.aligned.m16n8k16.row.col.f32.f16.f16.f32 " \
        "{%0,%1,%2,%3}, {%4,%5,%6,%7}, {%8,%9}, {%0,%1,%2,%3};" \
        : "+f"((d)[0]), "+f"((d)[1]), "+f"((d)[2]), "+f"((d)[3]) \
        : "r"((a)[0]), "r"((a)[1]), "r"((a)[2]), "r"((a)[3]), \
          "r"(b0v), "r"(b1v))

// ---------------------------------------------------------------------------
// Kernel 1: binarize + fp16 + NCHW->NHWC (conflict-free half2 transpose)
// ---------------------------------------------------------------------------
__global__ void binsplit_kernel(const float* __restrict__ x) {
    __shared__ __half2 s[32][33];
    const int n = blockIdx.z, ci0 = blockIdx.y * 32, pos0 = blockIdx.x * 64;
    const int tid = threadIdx.x;

    #pragma unroll
    for (int i = 0; i < 4; i++) {
        int unit = tid + i * 256;
        int cl = unit >> 5;
        int pp = unit & 31;
        float2 v = *reinterpret_cast<const float2*>(
            x + ((size_t)(n * CIN + ci0 + cl) * HW + pos0 + pp * 2));
        float m = 0.5f * (fabsf(v.x) + fabsf(v.y));
        float a = (v.x == 0.0f) ? 0.0f : copysignf(m, v.x);
        float b = (v.y == 0.0f) ? 0.0f : copysignf(m, v.y);
        s[pp][cl] = __halves2half2(__float2half(a), __float2half(b));
    }
    __syncthreads();

    const int pl = tid >> 2;
    const int c8 = tid & 3;
    const int pp = pl >> 1;
    const int hi = pl & 1;

    uint32_t w[4];
    #pragma unroll
    for (int k = 0; k < 4; k++) {
        __half2 t0 = s[pp][c8 * 8 + 2 * k];
        __half2 t1 = s[pp][c8 * 8 + 2 * k + 1];
        __half a0 = hi ? __high2half(t0) : __low2half(t0);
        __half a1 = hi ? __high2half(t1) : __low2half(t1);
        w[k] = (uint32_t)__half_as_ushort(a0) |
               ((uint32_t)__half_as_ushort(a1) << 16);
    }
    size_t dst = ((size_t)n * HW + pos0 + pl) * CIN + ci0 + c8 * 8;
    *reinterpret_cast<uint4*>(g_a + dst) = make_uint4(w[0], w[1], w[2], w[3]);
}

// ---------------------------------------------------------------------------
// Kernel 2: weights OIHW -> fp16 [tap][oc][ci]
// ---------------------------------------------------------------------------
__global__ void wsplit_kernel(const float* __restrict__ w) {
    int idx = blockIdx.x * blockDim.x + threadIdx.x;
    if (idx >= COUT * CIN * KTAPS) return;
    int oc  = idx / (CIN * KTAPS);
    int rem = idx % (CIN * KTAPS);
    int ci  = rem / KTAPS;
    int tap = rem % KTAPS;
    g_w[((size_t)tap * COUT + oc) * CIN + ci] = __float2half(w[idx]);
}

// ---------------------------------------------------------------------------
// Kernel 3: implicit-GEMM conv. CTA 128M x 256N, 8 warps (2x4), warp 64x64.
// 3-stage cp.async pipeline; fragment-level software pipelining inside stage.
// NOTES: - acc / fragment buffers indexed by compile-time values ONLY
//        - 256 threads => 255-reg budget
// ---------------------------------------------------------------------------
__global__ __launch_bounds__(THREADS, 1)
void conv_hmma_kernel(const float* __restrict__ bias, float* __restrict__ out) {
    extern __shared__ __align__(1024) char smem[];
    __shared__ float s_bias[COUT];

    const int tid  = threadIdx.x;
    const int warp = tid >> 5;
    const int lane = tid & 31;
    const int m0   = blockIdx.x * M_TILE;
    const uint32_t sb = smem_u32(smem);

    s_bias[tid] = bias[tid];

    // ---- producer geometry (chunk-invariant): 4 A segments per thread ----
    int a_h[4], a_w[4];
    uint32_t a_dst[4];
    const __half* a_base[4];
    #pragma unroll
    for (int i = 0; i < 4; i++) {
        int unit = tid + i * THREADS;          // 0..1023
        int r = unit >> 3, u = unit & 7;
        int m = m0 + r;
        int img = m / HW, pos = m % HW;
        a_h[i] = pos / HW_W;
        a_w[i] = pos - a_h[i] * HW_W;
        a_base[i] = g_a + (size_t)img * HW * CIN + u * 8;
        a_dst[i] = (uint32_t)(r * 128 + ((u ^ (r & 7)) << 4));
    }

    auto load_chunk = [&](int c, int buf) {
        const int tap = c >> 2, ci0 = (c & 3) * KC;
        const int dy = tap / 3 - 1, dx = tap % 3 - 1;
        uint32_t ab = sb + buf * STAGE_BYTES;
        #pragma unroll
        for (int i = 0; i < 4; i++) {
            int h2 = a_h[i] + dy, w2 = a_w[i] + dx;
            bool valid = ((unsigned)h2 < HW_H) && ((unsigned)w2 < HW_W);
            int hh = valid ? h2 : 0, ww = valid ? w2 : 0;
            const __half* src = a_base[i] + ((size_t)hh * HW_W + ww) * CIN + ci0;
            CP_ASYNC16(ab + a_dst[i], src, valid ? 16 : 0);
        }
        uint32_t bb = ab + A_BYTES;
        const __half* wsrc = g_w + (size_t)tap * COUT * CIN + ci0;
        #pragma unroll
        for (int i = 0; i < 8; i++) {
            int unit = tid + i * THREADS;      // 0..2047
            int r = unit >> 3, u = unit & 7;
            CP_ASYNC16(bb + (uint32_t)(r * 128 + ((u ^ (r & 7)) << 4)),
                       wsrc + r * CIN + u * 8, 16);
        }
    };

    load_chunk(0, 0); CP_COMMIT();
    load_chunk(1, 1); CP_COMMIT();

    // ---- consumer geometry ----
    const int wm = warp >> 2, wn = warp & 3;           // 2 x 4 warp grid
    const int arow0 = wm * 64 + (lane & 15);           // + mt*16
    const int ach   = lane >> 4;
    const int brow0 = wn * 64 + (lane & 7) + ((lane >> 4) << 3);  // + ng*16
    const int bch   = (lane >> 3) & 1;

    float acc[4][8][4];
    #pragma unroll
    for (int i = 0; i < 4; i++)
        #pragma unroll
        for (int j = 0; j < 8; j++)
            #pragma unroll
            for (int k = 0; k < 4; k++) acc[i][j][k] = 0.0f;

    // Software-pipelined stage: fragments double-buffered, prefetch 1 ahead.
    auto compute_stage = [&](int buf) {
        uint32_t Ab = sb + buf * STAGE_BYTES;
        uint32_t Bb = Ab + A_BYTES;
        auto aaddr = [&](int mt, int ks) {
            int row = arow0 + mt * 16;
            return Ab + (uint32_t)(row * 128 +
                   (((ks * 2 + ach) ^ (row & 7)) << 4));
        };
        auto baddr = [&](int ng, int ks) {
            int row = brow0 + ng * 16;
            return Bb + (uint32_t)(row * 128 +
                   (((ks * 2 + bch) ^ (row & 7)) << 4));
        };
        uint32_t b[2][4][4];       // [ks&1][ng][frag]
        uint32_t a[2][4];          // [mt&1][frag]

        #pragma unroll
        for (int ng = 0; ng < 4; ng++) LDSM_X4(b[0][ng], baddr(ng, 0));
        LDSM_X4(a[0], aaddr(0, 0));

        #pragma unroll
        for (int ks = 0; ks < 4; ks++) {
            #pragma unroll
            for (int mt = 0; mt < 4; mt++) {
                // prefetch next fragments before consuming current ones
                if (mt < 3) {
                    LDSM_X4(a[(mt + 1) & 1], aaddr(mt + 1, ks));
                } else if (ks < 3) {
                    #pragma unroll
                    for (int ng = 0; ng < 4; ng++)
                        LDSM_X4(b[(ks + 1) & 1][ng], baddr(ng, ks + 1));
                    LDSM_X4(a[0], aaddr(0, ks + 1));   // (3+1)&1 == 0
                }
                #pragma unroll
                for (int ng = 0; ng < 4; ng++) {
                    MMA16816(acc[mt][2 * ng],     a[mt & 1],
                             b[ks & 1][ng][0], b[ks & 1][ng][1]);
                    MMA16816(acc[mt][2 * ng + 1], a[mt & 1],
                             b[ks & 1][ng][2], b[ks & 1][ng][3]);
                }
            }
        }
    };

    // ---- main loop ----
    int st = 0, ld = 2;
    #pragma unroll 1
    for (int c = 0; c < NCHUNKS; c++) {
        CP_WAIT1();
        __syncthreads();
        if (c + 2 < NCHUNKS) load_chunk(c + 2, ld);
        CP_COMMIT();
        ld = (ld == 2) ? 0 : ld + 1;
        compute_stage(st);
        st = (st == 2) ? 0 : st + 1;
    }

    // ---- epilogue: FULLY UNROLLED (acc indices compile-time) ----
    __syncthreads();
    float* epi = reinterpret_cast<float*>(smem) + warp * (64 * 33);
    #pragma unroll
    for (int mh = 0; mh < 2; mh++) {                 // compile-time
        #pragma unroll
        for (int mtl = 0; mtl < 2; mtl++) {          // compile-time
            #pragma unroll
            for (int nt = 0; nt < 8; nt++) {
                int nloc = nt * 8 + (lane & 3) * 2;
                int mloc = mtl * 16 + (lane >> 2);
                epi[ nloc      * 33 + mloc    ] = acc[mh * 2 + mtl][nt][0];
                epi[(nloc + 1) * 33 + mloc    ] = acc[mh * 2 + mtl][nt][1];
                epi[ nloc      * 33 + mloc + 8] = acc[mh * 2 + mtl][nt][2];
                epi[(nloc + 1) * 33 + mloc + 8] = acc[mh * 2 + mtl][nt][3];
            }
        }
        __syncwarp();
        {
            int m   = m0 + wm * 64 + mh * 32 + lane;
            int img = m / HW, pos = m % HW;
            float* ob = out + (size_t)img * COUT * HW + pos;
            #pragma unroll 4
            for (int nloc = 0; nloc < 64; nloc++) {
                int oc = wn * 64 + nloc;
                ob[(size_t)oc * HW] = epi[nloc * 33 + lane] + s_bias[oc];
            }
        }
        __syncwarp();
    }
}

// ---------------------------------------------------------------------------
// Launch
// ---------------------------------------------------------------------------
extern "C" void kernel_launch(void* const* d_in, const int* in_sizes, int n_in,
                              void* d_out, int out_size) {
    const float* x      = (const float*)d_in[0];   // [32,256,56,56]
    const float* weight = (const float*)d_in[1];   // [256,256,3,3]
    const float* bias   = (const float*)d_in[2];   // [256]
    float* out = (float*)d_out;

    {
        dim3 grid(HW / 64, CIN / 32, BATCH);       // (49, 8, 32)
        binsplit_kernel<<<grid, 256>>>(x);
    }
    {
        int n = COUT * CIN * KTAPS;
        wsplit_kernel<<<(n + 255) / 256, 256>>>(weight);
    }
    {
        cudaFuncSetAttribute(conv_hmma_kernel,
                             cudaFuncAttributeMaxDynamicSharedMemorySize,
                             SMEM_DYN);
        int m_tiles = M_TOT / M_TILE;              // 784
        conv_hmma_kernel<<<m_tiles, THREADS, SMEM_DYN>>>(bias, out);
    }
    (void)in_sizes; (void)n_in; (void)out_size;
}

// round 10
// speedup vs baseline: 1.1240x; 1.1240x over previous
#include <cuda_runtime.h>
#include <cuda_fp16.h>
#include <math.h>
#include <stdint.h>

// ---------------------------------------------------------------------------
// Problem constants
// ---------------------------------------------------------------------------
#define BATCH 32
#define CIN   256
#define COUT  256
#define HW_H  56
#define HW_W  56
#define HW    3136
#define KTAPS 9
#define M_TOT (BATCH * HW)               // 100352

#define M_TILE   128
#define N_TILE   128                     // N split over blockIdx.y (2 CTAs/SM)
#define THREADS  128                     // 4 warps (2x2), warp tile 64x64
#define KC       64                      // ci per K chunk (4 k16 steps)
#define NCHUNKS  (KTAPS * (CIN / KC))    // 36
#define A_BYTES  (M_TILE * KC * 2)       // 16384
#define B_BYTES  (N_TILE * KC * 2)       // 16384
#define STAGE_BYTES (A_BYTES + B_BYTES)  // 32768
#define SMEM_DYN (3 * STAGE_BYTES)       // 98304 -> 2 CTAs/SM

// ---------------------------------------------------------------------------
// Global scratch
// ---------------------------------------------------------------------------
__device__ __align__(16) __half g_a[(size_t)M_TOT * CIN];    // NHWC fp16
__device__ __align__(16) __half g_w[KTAPS * COUT * CIN];     // [tap][oc][ci]

// ---------------------------------------------------------------------------
// PTX helpers (compute_103-safe: sm_80-class features only)
// ---------------------------------------------------------------------------
__device__ __forceinline__ uint32_t smem_u32(const void* p) {
    uint32_t a;
    asm("{ .reg .u64 t; cvta.to.shared.u64 t, %1; cvt.u32.u64 %0, t; }"
        : "=r"(a) : "l"(p));
    return a;
}
#define CP_ASYNC16(dst, src, sz) \
    asm volatile("cp.async.ca.shared.global [%0], [%1], 16, %2;" \
        :: "r"(dst), "l"(src), "r"(sz) : "memory")
#define CP_COMMIT() asm volatile("cp.async.commit_group;" ::: "memory")
#define CP_WAIT1()  asm volatile("cp.async.wait_group 1;" ::: "memory")

#define LDSM_X4(r, addr) \
    asm volatile("ldmatrix.sync.aligned.m8n8.x4.shared.b16 {%0,%1,%2,%3}, [%4];" \
        : "=r"((r)[0]), "=r"((r)[1]), "=r"((r)[2]), "=r"((r)[3]) : "r"(addr))

#define MMA16816(d, a, b0v, b1v) \
    asm volatile("mma.sync.aligned.m16n8k16.row.col.f32.f16.f16.f32 " \
        "{%0,%1,%2,%3}, {%4,%5,%6,%7}, {%8,%9}, {%0,%1,%2,%3};" \
        : "+f"((d)[0]), "+f"((d)[1]), "+f"((d)[2]), "+f"((d)[3]) \
        : "r"((a)[0]), "r"((a)[1]), "r"((a)[2]), "r"((a)[3]), \
          "r"(b0v), "r"(b1v))

// ---------------------------------------------------------------------------
// Kernel 1: binarize + fp16 + NCHW->NHWC (conflict-free half2 transpose)
// ---------------------------------------------------------------------------
__global__ void binsplit_kernel(const float* __restrict__ x) {
    __shared__ __half2 s[32][33];
    const int n = blockIdx.z, ci0 = blockIdx.y * 32, pos0 = blockIdx.x * 64;
    const int tid = threadIdx.x;

    #pragma unroll
    for (int i = 0; i < 4; i++) {
        int unit = tid + i * 256;
        int cl = unit >> 5;
        int pp = unit & 31;
        float2 v = *reinterpret_cast<const float2*>(
            x + ((size_t)(n * CIN + ci0 + cl) * HW + pos0 + pp * 2));
        float m = 0.5f * (fabsf(v.x) + fabsf(v.y));
        float a = (v.x == 0.0f) ? 0.0f : copysignf(m, v.x);
        float b = (v.y == 0.0f) ? 0.0f : copysignf(m, v.y);
        s[pp][cl] = __halves2half2(__float2half(a), __float2half(b));
    }
    __syncthreads();

    const int pl = tid >> 2;
    const int c8 = tid & 3;
    const int pp = pl >> 1;
    const int hi = pl & 1;

    uint32_t w[4];
    #pragma unroll
    for (int k = 0; k < 4; k++) {
        __half2 t0 = s[pp][c8 * 8 + 2 * k];
        __half2 t1 = s[pp][c8 * 8 + 2 * k + 1];
        __half a0 = hi ? __high2half(t0) : __low2half(t0);
        __half a1 = hi ? __high2half(t1) : __low2half(t1);
        w[k] = (uint32_t)__half_as_ushort(a0) |
               ((uint32_t)__half_as_ushort(a1) << 16);
    }
    size_t dst = ((size_t)n * HW + pos0 + pl) * CIN + ci0 + c8 * 8;
    *reinterpret_cast<uint4*>(g_a + dst) = make_uint4(w[0], w[1], w[2], w[3]);
}

// ---------------------------------------------------------------------------
// Kernel 2: weights OIHW -> fp16 [tap][oc][ci]
// ---------------------------------------------------------------------------
__global__ void wsplit_kernel(const float* __restrict__ w) {
    int idx = blockIdx.x * blockDim.x + threadIdx.x;
    if (idx >= COUT * CIN * KTAPS) return;
    int oc  = idx / (CIN * KTAPS);
    int rem = idx % (CIN * KTAPS);
    int ci  = rem / KTAPS;
    int tap = rem % KTAPS;
    g_w[((size_t)tap * COUT + oc) * CIN + ci] = __float2half(w[idx]);
}

// ---------------------------------------------------------------------------
// Kernel 3: implicit-GEMM conv. CTA 128M x 128N, 4 warps (2x2), warp 64x64.
// 3-stage cp.async pipeline; 2 CTAs co-resident per SM -> barrier overlap.
// NOTES: - acc indexed by compile-time values ONLY (reg demotion otherwise)
// ---------------------------------------------------------------------------
__global__ __launch_bounds__(THREADS, 2)
void conv_hmma_kernel(const float* __restrict__ bias, float* __restrict__ out) {
    extern __shared__ __align__(1024) char smem[];
    __shared__ float s_bias[N_TILE];

    const int tid  = threadIdx.x;
    const int warp = tid >> 5;
    const int lane = tid & 31;
    const int m0   = blockIdx.x * M_TILE;
    const int oc0  = blockIdx.y * N_TILE;
    const uint32_t sb = smem_u32(smem);

    s_bias[tid] = bias[oc0 + tid];

    // ---- producer geometry (chunk-invariant): 8 A segments per thread ----
    int a_h[8], a_w[8];
    uint32_t a_dst[8];
    const __half* a_base[8];
    #pragma unroll
    for (int i = 0; i < 8; i++) {
        int unit = tid + i * THREADS;          // 0..1023
        int r = unit >> 3, u = unit & 7;
        int m = m0 + r;
        int img = m / HW, pos = m % HW;
        a_h[i] = pos / HW_W;
        a_w[i] = pos - a_h[i] * HW_W;
        a_base[i] = g_a + (size_t)img * HW * CIN + u * 8;
        a_dst[i] = (uint32_t)(r * 128 + ((u ^ (r & 7)) << 4));
    }

    auto load_chunk = [&](int c, int buf) {
        const int tap = c >> 2, ci0 = (c & 3) * KC;
        const int dy = tap / 3 - 1, dx = tap % 3 - 1;
        uint32_t ab = sb + buf * STAGE_BYTES;
        #pragma unroll
        for (int i = 0; i < 8; i++) {
            int h2 = a_h[i] + dy, w2 = a_w[i] + dx;
            bool valid = ((unsigned)h2 < HW_H) && ((unsigned)w2 < HW_W);
            int hh = valid ? h2 : 0, ww = valid ? w2 : 0;
            const __half* src = a_base[i] + ((size_t)hh * HW_W + ww) * CIN + ci0;
            CP_ASYNC16(ab + a_dst[i], src, valid ? 16 : 0);
        }
        uint32_t bb = ab + A_BYTES;
        const __half* wsrc = g_w + (size_t)tap * COUT * CIN +
                             (size_t)oc0 * CIN + ci0;
        #pragma unroll
        for (int i = 0; i < 8; i++) {
            int unit = tid + i * THREADS;      // 0..1023
            int r = unit >> 3, u = unit & 7;
            CP_ASYNC16(bb + (uint32_t)(r * 128 + ((u ^ (r & 7)) << 4)),
                       wsrc + r * CIN + u * 8, 16);
        }
    };

    load_chunk(0, 0); CP_COMMIT();
    load_chunk(1, 1); CP_COMMIT();

    // ---- consumer geometry: 2x2 warp grid, warp tile 64x64 ----
    const int wm = warp >> 1, wn = warp & 1;
    const int arow0 = wm * 64 + (lane & 15);           // + mt*16
    const int ach   = lane >> 4;
    const int brow0 = wn * 64 + (lane & 7) + ((lane >> 4) << 3);  // + ng*16
    const int bch   = (lane >> 3) & 1;

    float acc[4][8][4];
    #pragma unroll
    for (int i = 0; i < 4; i++)
        #pragma unroll
        for (int j = 0; j < 8; j++)
            #pragma unroll
            for (int k = 0; k < 4; k++) acc[i][j][k] = 0.0f;

    auto compute_stage = [&](int buf) {
        uint32_t Ab = sb + buf * STAGE_BYTES;
        uint32_t Bb = Ab + A_BYTES;
        #pragma unroll
        for (int ks = 0; ks < 4; ks++) {
            uint32_t b[4][4];
            #pragma unroll
            for (int ng = 0; ng < 4; ng++) {
                int row = brow0 + ng * 16;
                LDSM_X4(b[ng], Bb + (uint32_t)(row * 128 +
                        (((ks * 2 + bch) ^ (row & 7)) << 4)));
            }
            #pragma unroll
            for (int mt = 0; mt < 4; mt++) {
                uint32_t a[4];
                int row = arow0 + mt * 16;
                LDSM_X4(a, Ab + (uint32_t)(row * 128 +
                        (((ks * 2 + ach) ^ (row & 7)) << 4)));
                #pragma unroll
                for (int ng = 0; ng < 4; ng++) {
                    MMA16816(acc[mt][2 * ng],     a, b[ng][0], b[ng][1]);
                    MMA16816(acc[mt][2 * ng + 1], a, b[ng][2], b[ng][3]);
                }
            }
        }
    };

    // ---- main loop ----
    int st = 0, ld = 2;
    #pragma unroll 1
    for (int c = 0; c < NCHUNKS; c++) {
        CP_WAIT1();
        __syncthreads();
        if (c + 2 < NCHUNKS) load_chunk(c + 2, ld);
        CP_COMMIT();
        ld = (ld == 2) ? 0 : ld + 1;
        compute_stage(st);
        st = (st == 2) ? 0 : st + 1;
    }

    // ---- epilogue: FULLY UNROLLED (acc indices compile-time) ----
    __syncthreads();
    float* epi = reinterpret_cast<float*>(smem) + warp * (64 * 33);
    #pragma unroll
    for (int mh = 0; mh < 2; mh++) {                 // compile-time
        #pragma unroll
        for (int mtl = 0; mtl < 2; mtl++) {          // compile-time
            #pragma unroll
            for (int nt = 0; nt < 8; nt++) {
                int nloc = nt * 8 + (lane & 3) * 2;
                int mloc = mtl * 16 + (lane >> 2);
                epi[ nloc      * 33 + mloc    ] = acc[mh * 2 + mtl][nt][0];
                epi[(nloc + 1) * 33 + mloc    ] = acc[mh * 2 + mtl][nt][1];
                epi[ nloc      * 33 + mloc + 8] = acc[mh * 2 + mtl][nt][2];
                epi[(nloc + 1) * 33 + mloc + 8] = acc[mh * 2 + mtl][nt][3];
            }
        }
        __syncwarp();
        {
            int m   = m0 + wm * 64 + mh * 32 + lane;
            int img = m / HW, pos = m % HW;
            float* ob = out + (size_t)img * COUT * HW + pos;
            #pragma unroll 4
            for (int nloc = 0; nloc < 64; nloc++) {
                int oc = wn * 64 + nloc;
                ob[(size_t)(oc0 + oc) * HW] = epi[nloc * 33 + lane] +
                                              s_bias[oc];
            }
        }
        __syncwarp();
    }
}

// ---------------------------------------------------------------------------
// Launch
// ---------------------------------------------------------------------------
extern "C" void kernel_launch(void* const* d_in, const int* in_sizes, int n_in,
                              void* d_out, int out_size) {
    const float* x      = (const float*)d_in[0];   // [32,256,56,56]
    const float* weight = (const float*)d_in[1];   // [256,256,3,3]
    const float* bias   = (const float*)d_in[2];   // [256]
    float* out = (float*)d_out;

    {
        dim3 grid(HW / 64, CIN / 32, BATCH);       // (49, 8, 32)
        binsplit_kernel<<<grid, 256>>>(x);
    }
    {
        int n = COUT * CIN * KTAPS;
        wsplit_kernel<<<(n + 255) / 256, 256>>>(weight);
    }
    {
        cudaFuncSetAttribute(conv_hmma_kernel,
                             cudaFuncAttributeMaxDynamicSharedMemorySize,
                             SMEM_DYN);
        dim3 grid(M_TOT / M_TILE, COUT / N_TILE);  // (784, 2)
        conv_hmma_kernel<<<grid, THREADS, SMEM_DYN>>>(bias, out);
    }
    (void)in_sizes; (void)n_in; (void)out_size;
}

// round 11
// speedup vs baseline: 1.1804x; 1.0502x over previous
#include <cuda_runtime.h>
#include <cuda_fp16.h>
#include <math.h>
#include <stdint.h>

// ---------------------------------------------------------------------------
// Problem constants
// ---------------------------------------------------------------------------
#define BATCH 32
#define CIN   256
#define COUT  256
#define HW_H  56
#define HW_W  56
#define HW    3136
#define KTAPS 9
#define M_TOT (BATCH * HW)               // 100352

#define M_TILE   128
#define N_TILE   128                     // N split over blockIdx.y
#define THREADS  128                     // 4 warps (2x2), warp tile 64x64
#define KC       64                      // ci per K chunk (4 k16 steps)
#define NCHUNKS  (KTAPS * (CIN / KC))    // 36

// A halo tile: rows m0-57 .. m0+186 (244 rows incl. zero rows), one ci-chunk
#define A_ROWS   244
#define ZROW     242                     // rows 242,243 are guaranteed zero
#define A_TILE_B (A_ROWS * 128)          // 31232 bytes
#define B_BYTES  (N_TILE * KC * 2)       // 16384
#define B_OFF    (2 * A_TILE_B)          // 62464
#define SMEM_DYN (B_OFF + 3 * B_BYTES)   // 111616 -> 2 CTAs/SM

// ---------------------------------------------------------------------------
// Global scratch
// ---------------------------------------------------------------------------
__device__ __align__(16) __half g_a[(size_t)M_TOT * CIN];    // NHWC fp16
__device__ __align__(16) __half g_w[KTAPS * COUT * CIN];     // [tap][oc][ci]

// ---------------------------------------------------------------------------
// PTX helpers (compute_103-safe: sm_80-class features only)
// ---------------------------------------------------------------------------
__device__ __forceinline__ uint32_t smem_u32(const void* p) {
    uint32_t a;
    asm("{ .reg .u64 t; cvta.to.shared.u64 t, %1; cvt.u32.u64 %0, t; }"
        : "=r"(a) : "l"(p));
    return a;
}
#define CP_ASYNC16(dst, src, sz) \
    asm volatile("cp.async.ca.shared.global [%0], [%1], 16, %2;" \
        :: "r"(dst), "l"(src), "r"(sz) : "memory")
#define CP_COMMIT() asm volatile("cp.async.commit_group;" ::: "memory")
#define CP_WAIT1()  asm volatile("cp.async.wait_group 1;" ::: "memory")

#define LDSM_X4(r, addr) \
    asm volatile("ldmatrix.sync.aligned.m8n8.x4.shared.b16 {%0,%1,%2,%3}, [%4];" \
        : "=r"((r)[0]), "=r"((r)[1]), "=r"((r)[2]), "=r"((r)[3]) : "r"(addr))

#define MMA16816(d, a, b0v, b1v) \
    asm volatile("mma.sync.aligned.m16n8k16.row.col.f32.f16.f16.f32 " \
        "{%0,%1,%2,%3}, {%4,%5,%6,%7}, {%8,%9}, {%0,%1,%2,%3};" \
        : "+f"((d)[0]), "+f"((d)[1]), "+f"((d)[2]), "+f"((d)[3]) \
        : "r"((a)[0]), "r"((a)[1]), "r"((a)[2]), "r"((a)[3]), \
          "r"(b0v), "r"(b1v))

// ---------------------------------------------------------------------------
// Kernel 1: binarize + fp16 + NCHW->NHWC (conflict-free half2 transpose)
// ---------------------------------------------------------------------------
__global__ void binsplit_kernel(const float* __restrict__ x) {
    __shared__ __half2 s[32][33];
    const int n = blockIdx.z, ci0 = blockIdx.y * 32, pos0 = blockIdx.x * 64;
    const int tid = threadIdx.x;

    #pragma unroll
    for (int i = 0; i < 4; i++) {
        int unit = tid + i * 256;
        int cl = unit >> 5;
        int pp = unit & 31;
        float2 v = *reinterpret_cast<const float2*>(
            x + ((size_t)(n * CIN + ci0 + cl) * HW + pos0 + pp * 2));
        float m = 0.5f * (fabsf(v.x) + fabsf(v.y));
        float a = (v.x == 0.0f) ? 0.0f : copysignf(m, v.x);
        float b = (v.y == 0.0f) ? 0.0f : copysignf(m, v.y);
        s[pp][cl] = __halves2half2(__float2half(a), __float2half(b));
    }
    __syncthreads();

    const int pl = tid >> 2;
    const int c8 = tid & 3;
    const int pp = pl >> 1;
    const int hi = pl & 1;

    uint32_t w[4];
    #pragma unroll
    for (int k = 0; k < 4; k++) {
        __half2 t0 = s[pp][c8 * 8 + 2 * k];
        __half2 t1 = s[pp][c8 * 8 + 2 * k + 1];
        __half a0 = hi ? __high2half(t0) : __low2half(t0);
        __half a1 = hi ? __high2half(t1) : __low2half(t1);
        w[k] = (uint32_t)__half_as_ushort(a0) |
               ((uint32_t)__half_as_ushort(a1) << 16);
    }
    size_t dst = ((size_t)n * HW + pos0 + pl) * CIN + ci0 + c8 * 8;
    *reinterpret_cast<uint4*>(g_a + dst) = make_uint4(w[0], w[1], w[2], w[3]);
}

// ---------------------------------------------------------------------------
// Kernel 2: weights OIHW -> fp16 [tap][oc][ci]
// ---------------------------------------------------------------------------
__global__ void wsplit_kernel(const float* __restrict__ w) {
    int idx = blockIdx.x * blockDim.x + threadIdx.x;
    if (idx >= COUT * CIN * KTAPS) return;
    int oc  = idx / (CIN * KTAPS);
    int rem = idx % (CIN * KTAPS);
    int ci  = rem / KTAPS;
    int tap = rem % KTAPS;
    g_w[((size_t)tap * COUT + oc) * CIN + ci] = __float2half(w[idx]);
}

// ---------------------------------------------------------------------------
// Kernel 3: implicit-GEMM conv. CTA 128M x 128N, 4 warps (2x2), warp 64x64.
// A halo tile resident per ci-chunk (double-buffered); B 3-stage cp.async.
// ci-outer / tap-inner chunk order. 2 CTAs/SM for barrier overlap.
// NOTES: - acc indexed by compile-time values ONLY (reg demotion otherwise)
// ---------------------------------------------------------------------------
__global__ __launch_bounds__(THREADS, 2)
void conv_hmma_kernel(const float* __restrict__ bias, float* __restrict__ out) {
    extern __shared__ __align__(1024) char smem[];
    __shared__ float s_bias[N_TILE];

    const int tid  = threadIdx.x;
    const int warp = tid >> 5;
    const int lane = tid & 31;
    const int m0   = blockIdx.x * M_TILE;
    const int oc0  = blockIdx.y * N_TILE;
    const uint32_t sb = smem_u32(smem);

    s_bias[tid] = bias[oc0 + tid];

    // ---- A halo loader: 244 rows x 8 segs for one ci-chunk ----
    auto load_A = [&](int cic, int abuf) {
        uint32_t ab = sb + abuf * A_TILE_B;
        #pragma unroll
        for (int i = 0; i < 16; i++) {
            int unit = tid + i * THREADS;           // 0..2047, used < 1952
            if (unit < A_ROWS * 8) {
                int row = unit >> 3, seg = unit & 7;
                int m   = m0 - 57 + row;
                bool v  = (row < ZROW) && (m >= 0) && (m < M_TOT);
                int mc  = v ? m : 0;
                const __half* src = g_a + (size_t)mc * CIN + cic * KC + seg * 8;
                uint32_t dst = ab + (uint32_t)(row * 128 +
                               ((seg ^ (row & 7)) << 4));
                CP_ASYNC16(dst, src, v ? 16 : 0);
            }
        }
    };

    // ---- B loader: 128 oc x 64 ci for one (tap, ci-chunk) ----
    auto load_B = [&](int tap, int cic, int bbuf) {
        uint32_t bb = sb + B_OFF + bbuf * B_BYTES;
        const __half* wsrc = g_w + (size_t)tap * COUT * CIN +
                             (size_t)oc0 * CIN + cic * KC;
        #pragma unroll
        for (int i = 0; i < 8; i++) {
            int unit = tid + i * THREADS;           // 0..1023
            int r = unit >> 3, u = unit & 7;
            CP_ASYNC16(bb + (uint32_t)(r * 128 + ((u ^ (r & 7)) << 4)),
                       wsrc + r * CIN + u * 8, 16);
        }
    };

    // ---- consumer geometry: 2x2 warp grid, warp tile 64x64 ----
    const int wm = warp >> 1, wn = warp & 1;
    int hh[4], ww[4], r0[4];
    #pragma unroll
    for (int mt = 0; mt < 4; mt++) {
        int m_local = wm * 64 + mt * 16 + (lane & 15);
        int pos = (m0 + m_local) % HW;
        hh[mt] = pos / HW_W;
        ww[mt] = pos - hh[mt] * HW_W;
        r0[mt] = m_local + 57;
    }
    const int ach   = lane >> 4;
    const int brow0 = wn * 64 + (lane & 7) + ((lane >> 4) << 3);  // + ng*16
    const int bch   = (lane >> 3) & 1;

    float acc[4][8][4];
    #pragma unroll
    for (int i = 0; i < 4; i++)
        #pragma unroll
        for (int j = 0; j < 8; j++)
            #pragma unroll
            for (int k = 0; k < 4; k++) acc[i][j][k] = 0.0f;

    auto compute_chunk = [&](int tap, int abuf, int bbuf) {
        const int dy = tap / 3 - 1;
        const int dx = tap - (tap / 3) * 3 - 1;
        const int shift = dy * HW_W + dx;
        uint32_t Ab = sb + abuf * A_TILE_B;
        uint32_t Bb = sb + B_OFF + bbuf * B_BYTES;
        uint32_t rowbase[4]; int rx[4];
        #pragma unroll
        for (int mt = 0; mt < 4; mt++) {
            int h2 = hh[mt] + dy, w2 = ww[mt] + dx;
            bool v = ((unsigned)h2 < HW_H) && ((unsigned)w2 < HW_W);
            int row = v ? (r0[mt] + shift) : ZROW;
            rowbase[mt] = Ab + (uint32_t)(row * 128);
            rx[mt] = row & 7;
        }
        #pragma unroll
        for (int ks = 0; ks < 4; ks++) {
            uint32_t b[4][4];
            #pragma unroll
            for (int ng = 0; ng < 4; ng++) {
                int row = brow0 + ng * 16;
                LDSM_X4(b[ng], Bb + (uint32_t)(row * 128 +
                        (((ks * 2 + bch) ^ (row & 7)) << 4)));
            }
            #pragma unroll
            for (int mt = 0; mt < 4; mt++) {
                uint32_t a[4];
                LDSM_X4(a, rowbase[mt] +
                        (uint32_t)(((ks * 2 + ach) ^ rx[mt]) << 4));
                #pragma unroll
                for (int ng = 0; ng < 4; ng++) {
                    MMA16816(acc[mt][2 * ng],     a, b[ng][0], b[ng][1]);
                    MMA16816(acc[mt][2 * ng + 1], a, b[ng][2], b[ng][3]);
                }
            }
        }
    };

    // ---- pipeline prologue ----
    load_A(0, 0);
    load_B(0, 0, 0); CP_COMMIT();      // group: A0 + B0
    load_B(1, 0, 1); CP_COMMIT();      // group: B1

    // ---- main loop: ci-outer / tap-inner ----
    int tap = 0, cic = 0;              // compute chunk q
    int tap2 = 2, cic2 = 0;            // load chunk q+2
    int st = 0, ld = 2;
    #pragma unroll 1
    for (int q = 0; q < NCHUNKS; q++) {
        CP_WAIT1();
        __syncthreads();
        if (q + 2 < NCHUNKS) {
            load_B(tap2, cic2, ld);
            if (tap2 == 0) load_A(cic2, cic2 & 1);   // bundle A with this group
        }
        CP_COMMIT();
        ld = (ld == 2) ? 0 : ld + 1;
        compute_chunk(tap, cic & 1, st);
        st = (st == 2) ? 0 : st + 1;
        if (++tap == KTAPS) { tap = 0; cic++; }
        if (++tap2 == KTAPS) { tap2 = 0; cic2++; }
    }

    // ---- epilogue: FULLY UNROLLED (acc indices compile-time) ----
    __syncthreads();
    float* epi = reinterpret_cast<float*>(smem) + warp * (64 * 33);
    #pragma unroll
    for (int mh = 0; mh < 2; mh++) {                 // compile-time
        #pragma unroll
        for (int mtl = 0; mtl < 2; mtl++) {          // compile-time
            #pragma unroll
            for (int nt = 0; nt < 8; nt++) {
                int nloc = nt * 8 + (lane & 3) * 2;
                int mloc = mtl * 16 + (lane >> 2);
                epi[ nloc      * 33 + mloc    ] = acc[mh * 2 + mtl][nt][0];
                epi[(nloc + 1) * 33 + mloc    ] = acc[mh * 2 + mtl][nt][1];
                epi[ nloc      * 33 + mloc + 8] = acc[mh * 2 + mtl][nt][2];
                epi[(nloc + 1) * 33 + mloc + 8] = acc[mh * 2 + mtl][nt][3];
            }
        }
        __syncwarp();
        {
            int m   = m0 + wm * 64 + mh * 32 + lane;
            int img = m / HW, pos = m % HW;
            float* ob = out + (size_t)img * COUT * HW + pos;
            #pragma unroll 4
            for (int nloc = 0; nloc < 64; nloc++) {
                int oc = wn * 64 + nloc;
                ob[(size_t)(oc0 + oc) * HW] = epi[nloc * 33 + lane] +
                                              s_bias[oc];
            }
        }
        __syncwarp();
    }
}

// ---------------------------------------------------------------------------
// Launch
// ---------------------------------------------------------------------------
extern "C" void kernel_launch(void* const* d_in, const int* in_sizes, int n_in,
                              void* d_out, int out_size) {
    const float* x      = (const float*)d_in[0];   // [32,256,56,56]
    const float* weight = (const float*)d_in[1];   // [256,256,3,3]
    const float* bias   = (const float*)d_in[2];   // [256]
    float* out = (float*)d_out;

    {
        dim3 grid(HW / 64, CIN / 32, BATCH);       // (49, 8, 32)
        binsplit_kernel<<<grid, 256>>>(x);
    }
    {
        int n = COUT * CIN * KTAPS;
        wsplit_kernel<<<(n + 255) / 256, 256>>>(weight);
    }
    {
        cudaFuncSetAttribute(conv_hmma_kernel,
                             cudaFuncAttributeMaxDynamicSharedMemorySize,
                             SMEM_DYN);
        dim3 grid(M_TOT / M_TILE, COUT / N_TILE);  // (784, 2)
        conv_hmma_kernel<<<grid, THREADS, SMEM_DYN>>>(bias, out);
    }
    (void)in_sizes; (void)n_in; (void)out_size;
}

// round 13
// speedup vs baseline: 1.2477x; 1.0570x over previous
#include <cuda_runtime.h>
#include <cuda_fp16.h>
#include <math.h>
#include <stdint.h>

// ---------------------------------------------------------------------------
// Problem constants
// ---------------------------------------------------------------------------
#define BATCH 32
#define CIN   256
#define COUT  256
#define HW_H  56
#define HW_W  56
#define HW    3136
#define KTAPS 9
#define M_TOT (BATCH * HW)               // 100352

#define M_TILE   96
#define N_TILE   128
#define THREADS  128                     // 4 warps (2x2), warp tile 48x64
#define KC       64                      // ci per K chunk (4 k16 steps)
#define NCHUNKS  (KTAPS * (CIN / KC))    // 36
#define M_TILES  ((M_TOT + M_TILE - 1) / M_TILE)   // 1046 (last partial)

// A halo tile: rows m0-57 .. m0+152 (210 rows) + 2 zero rows, one ci-chunk
#define A_ROWS   212
#define ZROW     210
#define A_TILE_B (A_ROWS * 128)          // 27136
#define B_BYTES  (N_TILE * KC * 2)       // 16384
#define SMEM_DYN (A_TILE_B + 2 * B_BYTES) // 59904 -> 3 CTAs/SM

// ---------------------------------------------------------------------------
// Global scratch
// ---------------------------------------------------------------------------
__device__ __align__(16) __half g_a[(size_t)M_TOT * CIN];    // NHWC fp16
__device__ __align__(16) __half g_w[KTAPS * COUT * CIN];     // [tap][oc][ci]

// ---------------------------------------------------------------------------
// PTX helpers (compute_103-safe: sm_80-class features only)
// ---------------------------------------------------------------------------
__device__ __forceinline__ uint32_t smem_u32(const void* p) {
    uint32_t a;
    asm("{ .reg .u64 t; cvta.to.shared.u64 t, %1; cvt.u32.u64 %0, t; }"
        : "=r"(a) : "l"(p));
    return a;
}
#define CP_ASYNC16(dst, src, sz) \
    asm volatile("cp.async.cg.shared.global [%0], [%1], 16, %2;" \
        :: "r"(dst), "l"(src), "r"(sz) : "memory")
#define CP_COMMIT() asm volatile("cp.async.commit_group;" ::: "memory")
#define CP_WAIT0()  asm volatile("cp.async.wait_group 0;" ::: "memory")
#define CP_WAIT1()  asm volatile("cp.async.wait_group 1;" ::: "memory")

#define LDSM_X4(r, addr) \
    asm volatile("ldmatrix.sync.aligned.m8n8.x4.shared.b16 {%0,%1,%2,%3}, [%4];" \
        : "=r"((r)[0]), "=r"((r)[1]), "=r"((r)[2]), "=r"((r)[3]) : "r"(addr))

#define MMA16816(d, a, b0v, b1v) \
    asm volatile("mma.sync.aligned.m16n8k16.row.col.f32.f16.f16.f32 " \
        "{%0,%1,%2,%3}, {%4,%5,%6,%7}, {%8,%9}, {%0,%1,%2,%3};" \
        : "+f"((d)[0]), "+f"((d)[1]), "+f"((d)[2]), "+f"((d)[3]) \
        : "r"((a)[0]), "r"((a)[1]), "r"((a)[2]), "r"((a)[3]), \
          "r"(b0v), "r"(b1v))

// ---------------------------------------------------------------------------
// Kernel 1 (fused): binarize+NHWC transpose (z<32) AND weight transpose (z==32)
// ---------------------------------------------------------------------------
__global__ void prep_kernel(const float* __restrict__ x,
                            const float* __restrict__ w) {
    const int tid = threadIdx.x;

    if (blockIdx.z == 32) {
        // ---- weights OIHW -> fp16 [tap][oc][ci] ----
        int b = blockIdx.y * 49 + blockIdx.x;        // 0..391
        #pragma unroll
        for (int k = 0; k < 6; k++) {
            int idx = b * 1536 + k * 256 + tid;
            if (idx < COUT * CIN * KTAPS) {
                int oc  = idx / (CIN * KTAPS);
                int rem = idx % (CIN * KTAPS);
                int ci  = rem / KTAPS;
                int tap = rem % KTAPS;
                g_w[((size_t)tap * COUT + oc) * CIN + ci] = __float2half(w[idx]);
            }
        }
        return;
    }

    // ---- binarize + fp16 + NCHW->NHWC (conflict-free half2 transpose) ----
    __shared__ __half2 s[32][33];
    const int n = blockIdx.z, ci0 = blockIdx.y * 32, pos0 = blockIdx.x * 64;

    #pragma unroll
    for (int i = 0; i < 4; i++) {
        int unit = tid + i * 256;
        int cl = unit >> 5;
        int pp = unit & 31;
        float2 v = *reinterpret_cast<const float2*>(
            x + ((size_t)(n * CIN + ci0 + cl) * HW + pos0 + pp * 2));
        float m = 0.5f * (fabsf(v.x) + fabsf(v.y));
        float a = (v.x == 0.0f) ? 0.0f : copysignf(m, v.x);
        float b = (v.y == 0.0f) ? 0.0f : copysignf(m, v.y);
        s[pp][cl] = __halves2half2(__float2half(a), __float2half(b));
    }
    __syncthreads();

    const int pl = tid >> 2;
    const int c8 = tid & 3;
    const int pp = pl >> 1;
    const int hi = pl & 1;

    uint32_t wv[4];
    #pragma unroll
    for (int k = 0; k < 4; k++) {
        __half2 t0 = s[pp][c8 * 8 + 2 * k];
        __half2 t1 = s[pp][c8 * 8 + 2 * k + 1];
        __half a0 = hi ? __high2half(t0) : __low2half(t0);
        __half a1 = hi ? __high2half(t1) : __low2half(t1);
        wv[k] = (uint32_t)__half_as_ushort(a0) |
                ((uint32_t)__half_as_ushort(a1) << 16);
    }
    size_t dst = ((size_t)n * HW + pos0 + pl) * CIN + ci0 + c8 * 8;
    *reinterpret_cast<uint4*>(g_a + dst) = make_uint4(wv[0], wv[1], wv[2], wv[3]);
}

// ---------------------------------------------------------------------------
// Kernel 2: implicit-GEMM conv. CTA 96M x 128N, 4 warps (2x2), warp 48x64.
// Single-buffer A halo per ci-chunk + 2-stage B ring. 3 CTAs/SM.
// NOTES: - acc indexed by compile-time values ONLY (reg demotion otherwise)
//        - cp.async data is only visible cross-warp after wait + BARRIER:
//          every consume path must have __syncthreads() after its wait.
// ---------------------------------------------------------------------------
__global__ __launch_bounds__(THREADS, 3)
void conv_hmma_kernel(const float* __restrict__ bias, float* __restrict__ out) {
    extern __shared__ __align__(1024) char smem[];
    __shared__ float s_bias[N_TILE];

    const int tid  = threadIdx.x;
    const int warp = tid >> 5;
    const int lane = tid & 31;
    const int m0   = blockIdx.x * M_TILE;
    const int oc0  = blockIdx.y * N_TILE;
    const uint32_t sb = smem_u32(smem);

    s_bias[tid] = bias[oc0 + tid];

    // ---- A halo loader (single buffer): 212 rows x 8 segs, one ci-chunk ----
    auto load_A = [&](int cic) {
        #pragma unroll
        for (int i = 0; i < 14; i++) {
            int unit = tid + i * THREADS;           // 0..1791, used < 1696
            if (unit < A_ROWS * 8) {
                int row = unit >> 3, seg = unit & 7;
                int m   = m0 - 57 + row;
                bool v  = (row < ZROW) && (m >= 0) && (m < M_TOT);
                int mc  = v ? m : 0;
                const __half* src = g_a + (size_t)mc * CIN + cic * KC + seg * 8;
                uint32_t dst = sb + (uint32_t)(row * 128 +
                               ((seg ^ (row & 7)) << 4));
                CP_ASYNC16(dst, src, v ? 16 : 0);
            }
        }
    };

    // ---- B loader: 128 oc x 64 ci for one (tap, ci-chunk) ----
    auto load_B = [&](int tap, int cic, int bbuf) {
        uint32_t bb = sb + A_TILE_B + bbuf * B_BYTES;
        const __half* wsrc = g_w + (size_t)tap * COUT * CIN +
                             (size_t)oc0 * CIN + cic * KC;
        #pragma unroll
        for (int i = 0; i < 8; i++) {
            int unit = tid + i * THREADS;           // 0..1023
            int r = unit >> 3, u = unit & 7;
            CP_ASYNC16(bb + (uint32_t)(r * 128 + ((u ^ (r & 7)) << 4)),
                       wsrc + r * CIN + u * 8, 16);
        }
    };

    // ---- consumer geometry: 2x2 warp grid, warp tile 48x64 ----
    const int wm = warp >> 1, wn = warp & 1;
    int hh[3], ww[3], r0[3];
    #pragma unroll
    for (int mt = 0; mt < 3; mt++) {
        int m_local = wm * 48 + mt * 16 + (lane & 15);
        int pos = (m0 + m_local) % HW;              // safe even if m>=M_TOT
        hh[mt] = pos / HW_W;
        ww[mt] = pos - hh[mt] * HW_W;
        r0[mt] = m_local + 57;
    }
    const int ach   = lane >> 4;
    const int brow0 = wn * 64 + (lane & 7) + ((lane >> 4) << 3);  // + ng*16
    const int bch   = (lane >> 3) & 1;

    float acc[3][8][4];
    #pragma unroll
    for (int i = 0; i < 3; i++)
        #pragma unroll
        for (int j = 0; j < 8; j++)
            #pragma unroll
            for (int k = 0; k < 4; k++) acc[i][j][k] = 0.0f;

    auto compute_chunk = [&](int tap, int bbuf) {
        const int dy = tap / 3 - 1;
        const int dx = tap - (tap / 3) * 3 - 1;
        const int shift = dy * HW_W + dx;
        uint32_t Bb = sb + A_TILE_B + bbuf * B_BYTES;
        uint32_t rowbase[3]; int rx[3];
        #pragma unroll
        for (int mt = 0; mt < 3; mt++) {
            int h2 = hh[mt] + dy, w2 = ww[mt] + dx;
            bool v = ((unsigned)h2 < HW_H) && ((unsigned)w2 < HW_W);
            int row = v ? (r0[mt] + shift) : ZROW;
            rowbase[mt] = sb + (uint32_t)(row * 128);
            rx[mt] = row & 7;
        }
        #pragma unroll
        for (int ks = 0; ks < 4; ks++) {
            uint32_t b[4][4];
            #pragma unroll
            for (int ng = 0; ng < 4; ng++) {
                int row = brow0 + ng * 16;
                LDSM_X4(b[ng], Bb + (uint32_t)(row * 128 +
                        (((ks * 2 + bch) ^ (row & 7)) << 4)));
            }
            #pragma unroll
            for (int mt = 0; mt < 3; mt++) {
                uint32_t a[4];
                LDSM_X4(a, rowbase[mt] +
                        (uint32_t)(((ks * 2 + ach) ^ rx[mt]) << 4));
                #pragma unroll
                for (int ng = 0; ng < 4; ng++) {
                    MMA16816(acc[mt][2 * ng],     a, b[ng][0], b[ng][1]);
                    MMA16816(acc[mt][2 * ng + 1], a, b[ng][2], b[ng][3]);
                }
            }
        }
    };

    // ---- pipeline prologue: A0 + B0 in one group ----
    load_A(0);
    load_B(0, 0, 0);
    CP_COMMIT();

    // ---- main loop: ci-outer / tap-inner, 2-stage B ring ----
    int tap = 0, cic = 0;
    #pragma unroll 1
    for (int q = 0; q < NCHUNKS; q++) {
        CP_WAIT0();                 // B(q) (and any pending A) complete
        __syncthreads();            // visibility of B(q); ring slot retired
        bool newA = (tap == 0) && (q > 0);
        if (newA) { load_A(cic); CP_COMMIT(); }
        if (q + 1 < NCHUNKS) {
            int tapn = (tap == 8) ? 0 : tap + 1;
            int cicn = (tap == 8) ? cic + 1 : cic;
            load_B(tapn, cicn, (q + 1) & 1);
            CP_COMMIT();
        }
        if (newA) {
            CP_WAIT1();             // own A copies done; B(q+1) may fly
            __syncthreads();        // CROSS-WARP visibility of A (the R12 bug)
        }
        compute_chunk(tap, q & 1);
        if (++tap == KTAPS) { tap = 0; cic++; }
    }

    // ---- epilogue: smem transpose -> coalesced NCHW stores + bias ----
    __syncthreads();
    float* epi = reinterpret_cast<float*>(smem) + warp * (64 * 33);

    // phase 0: mt 0,1 (32 rows)
    #pragma unroll
    for (int mtl = 0; mtl < 2; mtl++) {
        #pragma unroll
        for (int nt = 0; nt < 8; nt++) {
            int nloc = nt * 8 + (lane & 3) * 2;
            int mloc = mtl * 16 + (lane >> 2);
            epi[ nloc      * 33 + mloc    ] = acc[mtl][nt][0];
            epi[(nloc + 1) * 33 + mloc    ] = acc[mtl][nt][1];
            epi[ nloc      * 33 + mloc + 8] = acc[mtl][nt][2];
            epi[(nloc + 1) * 33 + mloc + 8] = acc[mtl][nt][3];
        }
    }
    __syncwarp();
    {
        int m = m0 + wm * 48 + lane;
        if (m < M_TOT) {
            int img = m / HW, pos = m % HW;
            float* ob = out + (size_t)img * COUT * HW + pos;
            #pragma unroll 4
            for (int nloc = 0; nloc < 64; nloc++) {
                int oc = wn * 64 + nloc;
                ob[(size_t)(oc0 + oc) * HW] = epi[nloc * 33 + lane] +
                                              s_bias[oc];
            }
        }
    }
    __syncwarp();

    // phase 1: mt 2 (16 rows)
    #pragma unroll
    for (int nt = 0; nt < 8; nt++) {
        int nloc = nt * 8 + (lane & 3) * 2;
        int mloc = lane >> 2;
        epi[ nloc      * 33 + mloc    ] = acc[2][nt][0];
        epi[(nloc + 1) * 33 + mloc    ] = acc[2][nt][1];
        epi[ nloc      * 33 + mloc + 8] = acc[2][nt][2];
        epi[(nloc + 1) * 33 + mloc + 8] = acc[2][nt][3];
    }
    __syncwarp();
    if (lane < 16) {
        int m = m0 + wm * 48 + 32 + lane;
        if (m < M_TOT) {
            int img = m / HW, pos = m % HW;
            float* ob = out + (size_t)img * COUT * HW + pos;
            #pragma unroll 4
            for (int nloc = 0; nloc < 64; nloc++) {
                int oc = wn * 64 + nloc;
                ob[(size_t)(oc0 + oc) * HW] = epi[nloc * 33 + lane] +
                                              s_bias[oc];
            }
        }
    }
}

// ---------------------------------------------------------------------------
// Launch
// ---------------------------------------------------------------------------
extern "C" void kernel_launch(void* const* d_in, const int* in_sizes, int n_in,
                              void* d_out, int out_size) {
    const float* x      = (const float*)d_in[0];   // [32,256,56,56]
    const float* weight = (const float*)d_in[1];   // [256,256,3,3]
    const float* bias   = (const float*)d_in[2];   // [256]
    float* out = (float*)d_out;

    // 1) fused prologue: activations (z<32) + weights (z==32)
    {
        dim3 grid(HW / 64, CIN / 32, BATCH + 1);   // (49, 8, 33)
        prep_kernel<<<grid, 256>>>(x, weight);
    }
    // 2) HMMA implicit-GEMM conv
    {
        cudaFuncSetAttribute(conv_hmma_kernel,
                             cudaFuncAttributeMaxDynamicSharedMemorySize,
                             SMEM_DYN);
        dim3 grid(M_TILES, COUT / N_TILE);         // (1046, 2)
        conv_hmma_kernel<<<grid, THREADS, SMEM_DYN>>>(bias, out);
    }
    (void)in_sizes; (void)n_in; (void)out_size;
}